// round 5
// baseline (speedup 1.0000x reference)
#include <cuda_runtime.h>
#include <stdint.h>

// R4: third submission of this source. R3/R4 benches died in the GB300
// container before producing compile/correctness output; full audit found no
// OOB/alignment/capture violations (see round notes). Betting on infra flake
// once more; bisect planned if it recurs.

#define BATCH 65536
#define RNDS  64
#define FULLM 0xffffffffu
// 2x margin over worst-case half-ulp (2^-16 for |sum| < 512)
#define FLAG_T 3.0517578125e-5f

// ------------------------- static device scratch ---------------------------
__device__ __align__(16) uint32_t g_A [RNDS][256][8];   // (M != 0)
__device__ __align__(16) uint32_t g_Mp[RNDS][256][8];   // (M == +1)
__device__ __align__(16) uint32_t g_Mm[RNDS][256][8];   // (M == -1)
__device__ __align__(16) uint32_t g_P [2][32][256][8];  // tree ping-pong: linear part
__device__ __align__(16) uint32_t g_Q [2][32][256][8];  // tree ping-pong: affine part
__device__ __align__(16) uint32_t g_S [BATCH][8];       // packed state bits
__device__ __align__(16) uint32_t g_C [BATCH][8];       // packed floor(noise)&1
__device__ __align__(16) uint32_t g_MT[512][8];         // columns of [P | Q]
__device__ unsigned char g_flag[BATCH];                 // per-row danger flag

// ------------------------- kernel: fused packing ---------------------------
// blocks [0,2048): pack matrices; blocks [2048,10240): pack state/noise+flags
__global__ __launch_bounds__(256) void k_pack_all(
    const float* __restrict__ bits, const float* __restrict__ noise,
    const float* __restrict__ mats)
{
    int b = blockIdx.x, t = threadIdx.x, lane = t & 31;
    if (b < 2048) {
        int gw = (b * 256 + t) >> 5;          // 0..16383 = r*256 + i
        int r = gw >> 8, i = gw & 255;
        const float* rowp = mats + (size_t)gw * 256;
#pragma unroll
        for (int w = 0; w < 8; ++w) {
            float v = rowp[w * 32 + lane];
            uint32_t ap = __ballot_sync(FULLM, v != 0.0f);
            uint32_t mp = __ballot_sync(FULLM, v >  0.5f);
            uint32_t mm = __ballot_sync(FULLM, v < -0.5f);
            if (lane == 0) { g_A[r][i][w] = ap; g_Mp[r][i][w] = mp; g_Mm[r][i][w] = mm; }
        }
    } else {
        int row = ((b - 2048) * 256 + t) >> 5;  // 0..65535
        bool bad = false;
#pragma unroll
        for (int w = 0; w < 8; ++w) {
            float bv = bits [(size_t)row * 256 + w * 32 + lane];
            float nv = noise[(size_t)row * 256 + w * 32 + lane];
            uint32_t sw = __ballot_sync(FULLM, bv > 0.5f);
            uint32_t cw = __ballot_sync(FULLM, (((int)floorf(nv)) & 1) != 0);
            float d = ceilf(nv) - nv;
            bad = bad || (d > 0.0f && d < FLAG_T);
            if (lane == 0) { g_S[row][w] = sw; g_C[row][w] = cw; }
        }
        uint32_t anyb = __ballot_sync(FULLM, bad);
        if (lane == 0) g_flag[row] = anyb ? 1 : 0;
    }
}

// ------------------------- 4-Russians GF(2) matmul (in-block) --------------
// OUT[i] = H[i] (x) B  (^ ADD[i]),  for rows [r0, r0+128).  256 threads.
// Table: 64 chunks x 16 entries x 8 words, stride 9 (conflict-free LDS.32).
__device__ __forceinline__ void tree_matmul(
    const uint32_t (*H)[8], const uint32_t (*B)[8],
    const uint32_t (*ADD)[8], uint32_t (*OUT)[8], int r0)
{
    __shared__ uint32_t Ts[64 * 16 * 9];
    int t = threadIdx.x;
    {
        int c = t >> 2, g = (t & 3) * 2;      // thread builds words g,g+1 of chunk c
        uint32_t b0[4], b1[4];
#pragma unroll
        for (int j = 0; j < 4; ++j) { b0[j] = B[4*c + j][g]; b1[j] = B[4*c + j][g + 1]; }
        int base = c * 144;
        Ts[base + g] = 0; Ts[base + g + 1] = 0;
#pragma unroll
        for (int e = 1; e < 16; ++e) {
            int p = e & (e - 1); int j = __ffs(e) - 1;
            Ts[base + e * 9 + g]     = Ts[base + p * 9 + g]     ^ b0[j];
            Ts[base + e * 9 + g + 1] = Ts[base + p * 9 + g + 1] ^ b1[j];
        }
    }
    __syncthreads();
    int li = t >> 1, h = (t & 1) * 4;
    int i = r0 + li;
    uint4 h0 = *reinterpret_cast<const uint4*>(&H[i][0]);
    uint4 h1 = *reinterpret_cast<const uint4*>(&H[i][4]);
    uint32_t hw[8] = {h0.x, h0.y, h0.z, h0.w, h1.x, h1.y, h1.z, h1.w};
    uint32_t a0 = 0, a1 = 0, a2 = 0, a3 = 0;
#pragma unroll
    for (int c = 0; c < 64; ++c) {
        uint32_t idx = (hw[c >> 3] >> ((c & 7) * 4)) & 15u;
        const uint32_t* e = &Ts[c * 144 + idx * 9 + h];
        a0 ^= e[0]; a1 ^= e[1]; a2 ^= e[2]; a3 ^= e[3];
    }
    if (ADD) {
        a0 ^= ADD[i][h]; a1 ^= ADD[i][h + 1]; a2 ^= ADD[i][h + 2]; a3 ^= ADD[i][h + 3];
    }
    uint32_t* o = &OUT[i][h];
    o[0] = a0; o[1] = a1; o[2] = a2; o[3] = a3;
}

// ------------------------- kernel: tree level 1 ----------------------------
// node n: P = A[2n+1]*A[2n], Q = A[2n+1] ^ I.   grid (32,1,2) x 256
__global__ __launch_bounds__(256) void k_tree_l1()
{
    int n = blockIdx.x, r0 = blockIdx.z * 128;
    tree_matmul(g_A[2*n+1], g_A[2*n], nullptr, g_P[0][n], r0);
    int t = threadIdx.x;
    int li = t >> 1, h = (t & 1) * 4;
    int i = r0 + li;
#pragma unroll
    for (int j = 0; j < 4; ++j) {
        int w = h + j;
        uint32_t q = g_A[2*n+1][i][w];
        if (w == (i >> 5)) q ^= 1u << (i & 31);
        g_Q[0][n][i][w] = q;
    }
}

// ------------------------- kernel: generic tree level ----------------------
// grid (nodes, 2, 2) x 256.   y==0: P = Ph*Pl ;  y==1: Q = Ph*Ql ^ Qh
__global__ __launch_bounds__(256) void k_tree_lv(int src, int dst)
{
    int n = blockIdx.x, isQ = blockIdx.y, r0 = blockIdx.z * 128;
    if (isQ)
        tree_matmul(g_P[src][2*n+1], g_Q[src][2*n], g_Q[src][2*n+1], g_Q[dst][n], r0);
    else
        tree_matmul(g_P[src][2*n+1], g_P[src][2*n], nullptr, g_P[dst][n], r0);
}

// ------------------------- kernel: transpose [P|Q] -> columns --------------
__global__ __launch_bounds__(256) void k_transpose()
{
    int j    = blockIdx.x * 8 + (threadIdx.x >> 5);  // 0..511
    int lane = threadIdx.x & 31;
    int jj = j & 255;
    const uint32_t (*src)[8] = (j < 256) ? g_P[1][0] : g_Q[1][0];
#pragma unroll
    for (int w = 0; w < 8; ++w) {
        uint32_t bit = (src[32 * w + lane][jj >> 5] >> (jj & 31)) & 1u;
        uint32_t col = __ballot_sync(FULLM, bit != 0);
        if (lane == 0) g_MT[j][w] = col;
    }
}

// ------------------------- kernel: batch apply + f32 output ----------------
// out_row = P*s ^ Q*c via 4-bit tables; f32 expansion fused. grid 256 x 256.
__global__ __launch_bounds__(256) void k_batch(float* __restrict__ out)
{
    __shared__ uint32_t Ts[64 * 16 * 9];
    __shared__ uint32_t outS[256][8];
    int tid = threadIdx.x;
    int rowbase = blockIdx.x * 256;
    int row = rowbase + tid;
    uint32_t x[8], acc[8] = {0,0,0,0,0,0,0,0};
#pragma unroll
    for (int w = 0; w < 8; ++w) x[w] = g_S[row][w];

    int c = tid >> 2, g = (tid & 3) * 2;
    for (int pass = 0; pass < 2; ++pass) {
        __syncthreads();
        uint32_t b0[4], b1[4];
#pragma unroll
        for (int j = 0; j < 4; ++j) {
            b0[j] = g_MT[pass * 256 + 4 * c + j][g];
            b1[j] = g_MT[pass * 256 + 4 * c + j][g + 1];
        }
        int base = c * 144;
        Ts[base + g] = 0; Ts[base + g + 1] = 0;
#pragma unroll
        for (int e = 1; e < 16; ++e) {
            int p = e & (e - 1); int j = __ffs(e) - 1;
            Ts[base + e * 9 + g]     = Ts[base + p * 9 + g]     ^ b0[j];
            Ts[base + e * 9 + g + 1] = Ts[base + p * 9 + g + 1] ^ b1[j];
        }
        __syncthreads();
#pragma unroll 8
        for (int cc = 0; cc < 64; ++cc) {
            uint32_t idx = (x[cc >> 3] >> ((cc & 7) * 4)) & 15u;
            const uint32_t* e = &Ts[cc * 144 + idx * 9];
#pragma unroll
            for (int w = 0; w < 8; ++w) acc[w] ^= e[w];
        }
        if (pass == 0) {
#pragma unroll
            for (int w = 0; w < 8; ++w) x[w] = g_C[row][w];
        }
    }
#pragma unroll
    for (int w = 0; w < 8; ++w) outS[tid][w] = acc[w];
    __syncthreads();

    // coalesced f32 expansion: each iter a warp writes 512B contiguous
#pragma unroll 4
    for (int it = 0; it < 64; ++it) {
        int flat = it * 1024 + tid * 4;
        int lrow = flat >> 8, i0 = flat & 255;
        uint32_t wv = outS[lrow][i0 >> 5];
        int sh = i0 & 31;
        float4 v;
        v.x = ((wv >> sh)       & 1u) ? 1.0f : 0.0f;
        v.y = ((wv >> (sh + 1)) & 1u) ? 1.0f : 0.0f;
        v.z = ((wv >> (sh + 2)) & 1u) ? 1.0f : 0.0f;
        v.w = ((wv >> (sh + 3)) & 1u) ? 1.0f : 0.0f;
        *reinterpret_cast<float4*>(&out[(size_t)(rowbase + lrow) * 256 + i0]) = v;
    }
}

// ------------------------- kernel: exact fallback for flagged rows ---------
// warp gw scans rows [32gw, 32gw+32); whole warp processes each flagged row.
__global__ __launch_bounds__(256) void k_fixup(
    const float* __restrict__ bits, const float* __restrict__ noise,
    float* __restrict__ out)
{
    int gw   = (blockIdx.x * 256 + threadIdx.x) >> 5;   // 0..2047
    int lane = threadIdx.x & 31;
    uint32_t m = __ballot_sync(FULLM, g_flag[gw * 32 + lane] != 0);
    while (m) {
        int rbit = __ffs(m) - 1; m &= m - 1;
        int row = gw * 32 + rbit;
        uint32_t sw[8], cw[8], dg[8]; float nz[8];
#pragma unroll
        for (int j = 0; j < 8; ++j) {
            int i = 32 * j + lane;
            float bv = bits [(size_t)row * 256 + i];
            float nv = noise[(size_t)row * 256 + i];
            nz[j] = nv;
            sw[j] = __ballot_sync(FULLM, bv > 0.5f);
            cw[j] = __ballot_sync(FULLM, (((int)floorf(nv)) & 1) != 0);
            float d = ceilf(nv) - nv;
            dg[j] = __ballot_sync(FULLM, d > 0.0f && d < FLAG_T);
        }
        for (int r = 0; r < RNDS; ++r) {
            uint32_t nb[8];
#pragma unroll
            for (int j = 0; j < 8; ++j) {
                int i = 32 * j + lane;
                const uint32_t* A = g_A[r][i];
                int pc = 0;
#pragma unroll
                for (int w = 0; w < 8; ++w) pc += __popc(A[w] & sw[w]);
                uint32_t bit = (uint32_t)(pc & 1) ^ ((cw[j] >> lane) & 1u);
                if ((dg[j] >> lane) & 1u) {
                    const uint32_t* Pp = g_Mp[r][i];
                    const uint32_t* Mn = g_Mm[r][i];
                    int dot = 0;
#pragma unroll
                    for (int w = 0; w < 8; ++w)
                        dot += __popc(Pp[w] & sw[w]) - __popc(Mn[w] & sw[w]);
                    bit = (uint32_t)(((int)floorf((float)dot + nz[j])) & 1);
                }
                nb[j] = __ballot_sync(FULLM, bit != 0);
            }
#pragma unroll
            for (int j = 0; j < 8; ++j) sw[j] = nb[j];
        }
#pragma unroll
        for (int j = 0; j < 8; ++j) {
            int i = 32 * j + lane;
            out[(size_t)row * 256 + i] = ((sw[j] >> lane) & 1u) ? 1.0f : 0.0f;
        }
    }
}

// ------------------------- launch ------------------------------------------
extern "C" void kernel_launch(void* const* d_in, const int* in_sizes, int n_in,
                              void* d_out, int out_size)
{
    const float* bits  = (const float*)d_in[0];
    const float* noise = (const float*)d_in[1];
    const float* mats  = (const float*)d_in[2];
    float* out = (float*)d_out;

    k_pack_all<<<10240, 256>>>(bits, noise, mats);
    k_tree_l1<<<dim3(32, 1, 2), 256>>>();
    k_tree_lv<<<dim3(16, 2, 2), 256>>>(0, 1);
    k_tree_lv<<<dim3( 8, 2, 2), 256>>>(1, 0);
    k_tree_lv<<<dim3( 4, 2, 2), 256>>>(0, 1);
    k_tree_lv<<<dim3( 2, 2, 2), 256>>>(1, 0);
    k_tree_lv<<<dim3( 1, 2, 2), 256>>>(0, 1);
    k_transpose<<<64, 256>>>();
    k_batch<<<256, 256>>>(out);
    k_fixup<<<256, 256>>>(bits, noise, out);
}

// round 7
// speedup vs baseline: 3.7555x; 3.7555x over previous
#include <cuda_runtime.h>
#include <stdint.h>

// R6 resubmit of the R5-proposed source. R6 bench died in the GB300 container
// pre-compile (same infra signature as R1/R3/R4; identical sources have since
// passed). Block-per-flagged-row fixup is the key unbenched change.

#define BATCH 65536
#define RNDS  64
#define FULLM 0xffffffffu
// 2x margin over worst-case half-ulp (2^-16 for |sum| < 512)
#define FLAG_T 3.0517578125e-5f

// ------------------------- static device scratch ---------------------------
__device__ __align__(16) uint32_t g_A [RNDS][256][8];   // (M != 0)
__device__ __align__(16) uint32_t g_Mp[RNDS][256][8];   // (M == +1)
__device__ __align__(16) uint32_t g_Mm[RNDS][256][8];   // (M == -1)
__device__ __align__(16) uint32_t g_P [2][32][256][8];  // tree ping-pong: linear part
__device__ __align__(16) uint32_t g_Q [2][32][256][8];  // tree ping-pong: affine part
__device__ __align__(16) uint32_t g_S [BATCH][8];       // packed state bits
__device__ __align__(16) uint32_t g_C [BATCH][8];       // packed floor(noise)&1
__device__ __align__(16) uint32_t g_MT[512][8];         // columns of [P | Q]
__device__ int g_flagcnt;
__device__ int g_flaglist[BATCH];

// ------------------------- kernel: reset -----------------------------------
__global__ void k_reset() { g_flagcnt = 0; }

// ------------------------- kernel: fused packing ---------------------------
// blocks [0,2048): pack matrices; blocks [2048,10240): pack state/noise+flags
__global__ __launch_bounds__(256) void k_pack_all(
    const float* __restrict__ bits, const float* __restrict__ noise,
    const float* __restrict__ mats)
{
    int b = blockIdx.x, t = threadIdx.x, lane = t & 31;
    if (b < 2048) {
        int gw = (b * 256 + t) >> 5;          // 0..16383 = r*256 + i
        int r = gw >> 8, i = gw & 255;
        const float* rowp = mats + (size_t)gw * 256;
#pragma unroll
        for (int w = 0; w < 8; ++w) {
            float v = rowp[w * 32 + lane];
            uint32_t ap = __ballot_sync(FULLM, v != 0.0f);
            uint32_t mp = __ballot_sync(FULLM, v >  0.5f);
            uint32_t mm = __ballot_sync(FULLM, v < -0.5f);
            if (lane == 0) { g_A[r][i][w] = ap; g_Mp[r][i][w] = mp; g_Mm[r][i][w] = mm; }
        }
    } else {
        int row = ((b - 2048) * 256 + t) >> 5;  // 0..65535
        bool bad = false;
#pragma unroll
        for (int w = 0; w < 8; ++w) {
            float bv = bits [(size_t)row * 256 + w * 32 + lane];
            float nv = noise[(size_t)row * 256 + w * 32 + lane];
            uint32_t sw = __ballot_sync(FULLM, bv > 0.5f);
            uint32_t cw = __ballot_sync(FULLM, (((int)floorf(nv)) & 1) != 0);
            float d = ceilf(nv) - nv;
            bad = bad || (d > 0.0f && d < FLAG_T);
            if (lane == 0) { g_S[row][w] = sw; g_C[row][w] = cw; }
        }
        uint32_t anyb = __ballot_sync(FULLM, bad);
        if (lane == 0 && anyb) {
            int idx = atomicAdd(&g_flagcnt, 1);
            g_flaglist[idx] = row;
        }
    }
}

// ------------------------- 4-Russians GF(2) matmul (in-block) --------------
// OUT[i] = H[i] (x) B  (^ ADD[i]),  for rows [r0, r0+128).  256 threads.
// Table: 64 chunks x 16 entries x 8 words, stride 9 (conflict-free LDS.32).
// Table entries built independently in registers (no serial smem chain).
__device__ __forceinline__ void tree_matmul(
    const uint32_t (*H)[8], const uint32_t (*B)[8],
    const uint32_t (*ADD)[8], uint32_t (*OUT)[8], int r0)
{
    __shared__ uint32_t Ts[64 * 16 * 9];
    int t = threadIdx.x;
    {
        int c = t >> 2, g = (t & 3) * 2;      // thread builds words g,g+1 of chunk c
        uint32_t b0[4], b1[4];
#pragma unroll
        for (int j = 0; j < 4; ++j) { b0[j] = B[4*c + j][g]; b1[j] = B[4*c + j][g + 1]; }
        int base = c * 144;
#pragma unroll
        for (int e = 0; e < 16; ++e) {
            uint32_t v0 = 0, v1 = 0;
            if (e & 1) { v0 ^= b0[0]; v1 ^= b1[0]; }
            if (e & 2) { v0 ^= b0[1]; v1 ^= b1[1]; }
            if (e & 4) { v0 ^= b0[2]; v1 ^= b1[2]; }
            if (e & 8) { v0 ^= b0[3]; v1 ^= b1[3]; }
            Ts[base + e * 9 + g] = v0; Ts[base + e * 9 + g + 1] = v1;
        }
    }
    __syncthreads();
    int li = t >> 1, h = (t & 1) * 4;
    int i = r0 + li;
    uint4 h0 = *reinterpret_cast<const uint4*>(&H[i][0]);
    uint4 h1 = *reinterpret_cast<const uint4*>(&H[i][4]);
    uint32_t hw[8] = {h0.x, h0.y, h0.z, h0.w, h1.x, h1.y, h1.z, h1.w};
    uint32_t a0 = 0, a1 = 0, a2 = 0, a3 = 0;
#pragma unroll
    for (int c = 0; c < 64; ++c) {
        uint32_t idx = (hw[c >> 3] >> ((c & 7) * 4)) & 15u;
        const uint32_t* e = &Ts[c * 144 + idx * 9 + h];
        a0 ^= e[0]; a1 ^= e[1]; a2 ^= e[2]; a3 ^= e[3];
    }
    if (ADD) {
        a0 ^= ADD[i][h]; a1 ^= ADD[i][h + 1]; a2 ^= ADD[i][h + 2]; a3 ^= ADD[i][h + 3];
    }
    uint32_t* o = &OUT[i][h];
    o[0] = a0; o[1] = a1; o[2] = a2; o[3] = a3;
}

// ------------------------- kernel: tree level 1 ----------------------------
// node n: P = A[2n+1]*A[2n], Q = A[2n+1] ^ I.   grid (32,1,2) x 256
__global__ __launch_bounds__(256) void k_tree_l1()
{
    int n = blockIdx.x, r0 = blockIdx.z * 128;
    tree_matmul(g_A[2*n+1], g_A[2*n], nullptr, g_P[0][n], r0);
    int t = threadIdx.x;
    int li = t >> 1, h = (t & 1) * 4;
    int i = r0 + li;
#pragma unroll
    for (int j = 0; j < 4; ++j) {
        int w = h + j;
        uint32_t q = g_A[2*n+1][i][w];
        if (w == (i >> 5)) q ^= 1u << (i & 31);
        g_Q[0][n][i][w] = q;
    }
}

// ------------------------- kernel: generic tree level ----------------------
// grid (nodes, 2, 2) x 256.   y==0: P = Ph*Pl ;  y==1: Q = Ph*Ql ^ Qh
__global__ __launch_bounds__(256) void k_tree_lv(int src, int dst)
{
    int n = blockIdx.x, isQ = blockIdx.y, r0 = blockIdx.z * 128;
    if (isQ)
        tree_matmul(g_P[src][2*n+1], g_Q[src][2*n], g_Q[src][2*n+1], g_Q[dst][n], r0);
    else
        tree_matmul(g_P[src][2*n+1], g_P[src][2*n], nullptr, g_P[dst][n], r0);
}

// ------------------------- kernel: transpose [P|Q] -> columns --------------
__global__ __launch_bounds__(256) void k_transpose()
{
    int j    = blockIdx.x * 8 + (threadIdx.x >> 5);  // 0..511
    int lane = threadIdx.x & 31;
    int jj = j & 255;
    const uint32_t (*src)[8] = (j < 256) ? g_P[1][0] : g_Q[1][0];
#pragma unroll
    for (int w = 0; w < 8; ++w) {
        uint32_t bit = (src[32 * w + lane][jj >> 5] >> (jj & 31)) & 1u;
        uint32_t col = __ballot_sync(FULLM, bit != 0);
        if (lane == 0) g_MT[j][w] = col;
    }
}

// ------------------------- kernel: batch apply + f32 output ----------------
// out_row = P*s ^ Q*c via 4-bit tables; f32 expansion fused. grid 256 x 256.
__global__ __launch_bounds__(256) void k_batch(float* __restrict__ out)
{
    __shared__ uint32_t Ts[64 * 16 * 9];
    __shared__ uint32_t outS[256][8];
    int tid = threadIdx.x;
    int rowbase = blockIdx.x * 256;
    int row = rowbase + tid;
    uint32_t x[8], acc[8] = {0,0,0,0,0,0,0,0};
#pragma unroll
    for (int w = 0; w < 8; ++w) x[w] = g_S[row][w];

    int c = tid >> 2, g = (tid & 3) * 2;
    for (int pass = 0; pass < 2; ++pass) {
        __syncthreads();
        uint32_t b0[4], b1[4];
#pragma unroll
        for (int j = 0; j < 4; ++j) {
            b0[j] = g_MT[pass * 256 + 4 * c + j][g];
            b1[j] = g_MT[pass * 256 + 4 * c + j][g + 1];
        }
        int base = c * 144;
#pragma unroll
        for (int e = 0; e < 16; ++e) {
            uint32_t v0 = 0, v1 = 0;
            if (e & 1) { v0 ^= b0[0]; v1 ^= b1[0]; }
            if (e & 2) { v0 ^= b0[1]; v1 ^= b1[1]; }
            if (e & 4) { v0 ^= b0[2]; v1 ^= b1[2]; }
            if (e & 8) { v0 ^= b0[3]; v1 ^= b1[3]; }
            Ts[base + e * 9 + g] = v0; Ts[base + e * 9 + g + 1] = v1;
        }
        __syncthreads();
#pragma unroll 8
        for (int cc = 0; cc < 64; ++cc) {
            uint32_t idx = (x[cc >> 3] >> ((cc & 7) * 4)) & 15u;
            const uint32_t* e = &Ts[cc * 144 + idx * 9];
#pragma unroll
            for (int w = 0; w < 8; ++w) acc[w] ^= e[w];
        }
        if (pass == 0) {
#pragma unroll
            for (int w = 0; w < 8; ++w) x[w] = g_C[row][w];
        }
    }
#pragma unroll
    for (int w = 0; w < 8; ++w) outS[tid][w] = acc[w];
    __syncthreads();

    // coalesced f32 expansion: each iter a warp writes 512B contiguous
#pragma unroll 4
    for (int it = 0; it < 64; ++it) {
        int flat = it * 1024 + tid * 4;
        int lrow = flat >> 8, i0 = flat & 255;
        uint32_t wv = outS[lrow][i0 >> 5];
        int sh = i0 & 31;
        float4 v;
        v.x = ((wv >> sh)       & 1u) ? 1.0f : 0.0f;
        v.y = ((wv >> (sh + 1)) & 1u) ? 1.0f : 0.0f;
        v.z = ((wv >> (sh + 2)) & 1u) ? 1.0f : 0.0f;
        v.w = ((wv >> (sh + 3)) & 1u) ? 1.0f : 0.0f;
        *reinterpret_cast<float4*>(&out[(size_t)(rowbase + lrow) * 256 + i0]) = v;
    }
}

// ------------------------- kernel: exact fallback, block per flagged row ---
// 256 threads = 256 elements; state in smem; A rows prefetched 1 round ahead.
__global__ __launch_bounds__(256) void k_fixup(
    const float* __restrict__ bits, const float* __restrict__ noise,
    float* __restrict__ out)
{
    __shared__ uint32_t st[8];
    int nf = g_flagcnt;
    int i = threadIdx.x, w = i >> 5, lane = i & 31;
    for (int li = blockIdx.x; li < nf; li += gridDim.x) {
        int row = g_flaglist[li];
        float nv = noise[(size_t)row * 256 + i];
        float bv = bits [(size_t)row * 256 + i];
        uint32_t cbit = (uint32_t)(((int)floorf(nv)) & 1);
        float dd = ceilf(nv) - nv;
        bool danger = (dd > 0.0f && dd < FLAG_T);
        uint32_t b = __ballot_sync(FULLM, bv > 0.5f);
        if (lane == 0) st[w] = b;
        __syncthreads();

        uint4 a0 = *reinterpret_cast<const uint4*>(&g_A[0][i][0]);
        uint4 a1 = *reinterpret_cast<const uint4*>(&g_A[0][i][4]);
        uint4 p0, p1, m0, m1;
        if (danger) {
            p0 = *reinterpret_cast<const uint4*>(&g_Mp[0][i][0]);
            p1 = *reinterpret_cast<const uint4*>(&g_Mp[0][i][4]);
            m0 = *reinterpret_cast<const uint4*>(&g_Mm[0][i][0]);
            m1 = *reinterpret_cast<const uint4*>(&g_Mm[0][i][4]);
        }
        uint32_t bit = 0;
        for (int r = 0; r < RNDS; ++r) {
            uint32_t s0 = st[0], s1 = st[1], s2 = st[2], s3 = st[3];
            uint32_t s4 = st[4], s5 = st[5], s6 = st[6], s7 = st[7];
            __syncthreads();                    // all reads done before overwrite
            int pc = __popc(a0.x & s0) + __popc(a0.y & s1)
                   + __popc(a0.z & s2) + __popc(a0.w & s3)
                   + __popc(a1.x & s4) + __popc(a1.y & s5)
                   + __popc(a1.z & s6) + __popc(a1.w & s7);
            bit = ((uint32_t)pc & 1u) ^ cbit;
            if (danger) {
                int dot = __popc(p0.x & s0) - __popc(m0.x & s0)
                        + __popc(p0.y & s1) - __popc(m0.y & s1)
                        + __popc(p0.z & s2) - __popc(m0.z & s2)
                        + __popc(p0.w & s3) - __popc(m0.w & s3)
                        + __popc(p1.x & s4) - __popc(m1.x & s4)
                        + __popc(p1.y & s5) - __popc(m1.y & s5)
                        + __popc(p1.z & s6) - __popc(m1.z & s6)
                        + __popc(p1.w & s7) - __popc(m1.w & s7);
                bit = (uint32_t)(((int)floorf((float)dot + nv)) & 1);
            }
            if (r < RNDS - 1) {                 // prefetch next round (state-indep)
                a0 = *reinterpret_cast<const uint4*>(&g_A[r+1][i][0]);
                a1 = *reinterpret_cast<const uint4*>(&g_A[r+1][i][4]);
                if (danger) {
                    p0 = *reinterpret_cast<const uint4*>(&g_Mp[r+1][i][0]);
                    p1 = *reinterpret_cast<const uint4*>(&g_Mp[r+1][i][4]);
                    m0 = *reinterpret_cast<const uint4*>(&g_Mm[r+1][i][0]);
                    m1 = *reinterpret_cast<const uint4*>(&g_Mm[r+1][i][4]);
                }
            }
            uint32_t nb = __ballot_sync(FULLM, bit != 0);
            if (lane == 0) st[w] = nb;
            __syncthreads();
        }
        out[(size_t)row * 256 + i] = bit ? 1.0f : 0.0f;
        __syncthreads();
    }
}

// ------------------------- launch ------------------------------------------
extern "C" void kernel_launch(void* const* d_in, const int* in_sizes, int n_in,
                              void* d_out, int out_size)
{
    const float* bits  = (const float*)d_in[0];
    const float* noise = (const float*)d_in[1];
    const float* mats  = (const float*)d_in[2];
    float* out = (float*)d_out;

    k_reset<<<1, 1>>>();
    k_pack_all<<<10240, 256>>>(bits, noise, mats);
    k_tree_l1<<<dim3(32, 1, 2), 256>>>();
    k_tree_lv<<<dim3(16, 2, 2), 256>>>(0, 1);
    k_tree_lv<<<dim3( 8, 2, 2), 256>>>(1, 0);
    k_tree_lv<<<dim3( 4, 2, 2), 256>>>(0, 1);
    k_tree_lv<<<dim3( 2, 2, 2), 256>>>(1, 0);
    k_tree_lv<<<dim3( 1, 2, 2), 256>>>(0, 1);
    k_transpose<<<64, 256>>>();
    k_batch<<<256, 256>>>(out);
    k_fixup<<<2048, 256>>>(bits, noise, out);
}

// round 8
// speedup vs baseline: 3.8184x; 1.0168x over previous
#include <cuda_runtime.h>
#include <stdint.h>

#define BATCH 65536
#define RNDS  64
#define FULLM 0xffffffffu
// 2x margin over worst-case half-ulp (2^-16 for |sum| < 512)
#define FLAG_T 3.0517578125e-5f

// ------------------------- static device scratch ---------------------------
__device__ __align__(16) uint32_t g_A [RNDS][256][8];   // (M != 0)
__device__ __align__(16) uint32_t g_Mp[RNDS][256][8];   // (M == +1)
__device__ __align__(16) uint32_t g_Mm[RNDS][256][8];   // (M == -1)
__device__ __align__(16) uint32_t g_P [2][32][256][8];  // tree ping-pong: linear part
__device__ __align__(16) uint32_t g_Q [2][32][256][8];  // tree ping-pong: affine part
__device__ __align__(16) uint32_t g_S [BATCH][8];       // packed state bits
__device__ __align__(16) uint32_t g_C [BATCH][8];       // packed floor(noise)&1
__device__ __align__(16) uint32_t g_MT[512][8];         // columns of [P | Q]
__device__ int g_flagcnt;
__device__ int g_flaglist[BATCH];

// ------------------------- kernel: reset -----------------------------------
__global__ void k_reset() { g_flagcnt = 0; }

// ------------------------- kernel: fused packing ---------------------------
// blocks [0,2048): pack matrices; blocks [2048,10240): pack state/noise+flags
__global__ __launch_bounds__(256) void k_pack_all(
    const float* __restrict__ bits, const float* __restrict__ noise,
    const float* __restrict__ mats)
{
    int b = blockIdx.x, t = threadIdx.x, lane = t & 31;
    if (b < 2048) {
        int gw = (b * 256 + t) >> 5;          // 0..16383 = r*256 + i
        int r = gw >> 8, i = gw & 255;
        const float* rowp = mats + (size_t)gw * 256;
#pragma unroll
        for (int w = 0; w < 8; ++w) {
            float v = rowp[w * 32 + lane];
            uint32_t ap = __ballot_sync(FULLM, v != 0.0f);
            uint32_t mp = __ballot_sync(FULLM, v >  0.5f);
            uint32_t mm = __ballot_sync(FULLM, v < -0.5f);
            if (lane == 0) { g_A[r][i][w] = ap; g_Mp[r][i][w] = mp; g_Mm[r][i][w] = mm; }
        }
    } else {
        int row = ((b - 2048) * 256 + t) >> 5;  // 0..65535
        bool bad = false;
#pragma unroll
        for (int w = 0; w < 8; ++w) {
            float bv = bits [(size_t)row * 256 + w * 32 + lane];
            float nv = noise[(size_t)row * 256 + w * 32 + lane];
            uint32_t sw = __ballot_sync(FULLM, bv > 0.5f);
            uint32_t cw = __ballot_sync(FULLM, (((int)floorf(nv)) & 1) != 0);
            float d = ceilf(nv) - nv;
            bad = bad || (d > 0.0f && d < FLAG_T);
            if (lane == 0) { g_S[row][w] = sw; g_C[row][w] = cw; }
        }
        uint32_t anyb = __ballot_sync(FULLM, bad);
        if (lane == 0 && anyb) {
            int idx = atomicAdd(&g_flagcnt, 1);
            g_flaglist[idx] = row;
        }
    }
}

// ------------------------- 4-Russians GF(2) matmul, 64 rows/block ----------
// OUT[i] = H[i] (x) B  (^ ADD[i]) for rows [r0, r0+64).  256 threads.
// Table stride 10 words -> LDS.64 pair loads, idx*10 covers all even banks.
// 4 threads per row (16 chunks each), combined via 2 shfl_xor rounds.
__device__ __forceinline__ void tree_matmul64(
    const uint32_t (*H)[8], const uint32_t (*B)[8],
    const uint32_t (*ADD)[8], uint32_t (*OUT)[8], int r0)
{
    __shared__ uint32_t Ts[64 * 16 * 10];     // 40960 B
    int t = threadIdx.x;
    {
        int c = t >> 2, g = (t & 3) * 2;      // thread builds words g,g+1 of chunk c
        uint32_t b0[4], b1[4];
#pragma unroll
        for (int j = 0; j < 4; ++j) { b0[j] = B[4*c + j][g]; b1[j] = B[4*c + j][g + 1]; }
        int base = c * 160;
#pragma unroll
        for (int e = 0; e < 16; ++e) {
            uint32_t v0 = 0, v1 = 0;
            if (e & 1) { v0 ^= b0[0]; v1 ^= b1[0]; }
            if (e & 2) { v0 ^= b0[1]; v1 ^= b1[1]; }
            if (e & 4) { v0 ^= b0[2]; v1 ^= b1[2]; }
            if (e & 8) { v0 ^= b0[3]; v1 ^= b1[3]; }
            Ts[base + e * 10 + g] = v0; Ts[base + e * 10 + g + 1] = v1;
        }
    }
    __syncthreads();

    int row = t >> 2, q = t & 3;              // 64 rows, 4 k-quarters
    int i = r0 + row;
    uint32_t hw0 = H[i][2 * q], hw1 = H[i][2 * q + 1];
    uint32_t a0 = 0, a1 = 0, a2 = 0, a3 = 0, a4 = 0, a5 = 0, a6 = 0, a7 = 0;
#pragma unroll
    for (int k = 0; k < 16; ++k) {
        int cc = 16 * q + k;
        uint32_t idx = ((k < 8 ? hw0 : hw1) >> ((k & 7) * 4)) & 15u;
        const uint2* e = reinterpret_cast<const uint2*>(&Ts[cc * 160 + idx * 10]);
        uint2 e0 = e[0], e1 = e[1], e2 = e[2], e3 = e[3];
        a0 ^= e0.x; a1 ^= e0.y; a2 ^= e1.x; a3 ^= e1.y;
        a4 ^= e2.x; a5 ^= e2.y; a6 ^= e3.x; a7 ^= e3.y;
    }
#pragma unroll
    for (int m = 1; m <= 2; m <<= 1) {
        a0 ^= __shfl_xor_sync(FULLM, a0, m); a1 ^= __shfl_xor_sync(FULLM, a1, m);
        a2 ^= __shfl_xor_sync(FULLM, a2, m); a3 ^= __shfl_xor_sync(FULLM, a3, m);
        a4 ^= __shfl_xor_sync(FULLM, a4, m); a5 ^= __shfl_xor_sync(FULLM, a5, m);
        a6 ^= __shfl_xor_sync(FULLM, a6, m); a7 ^= __shfl_xor_sync(FULLM, a7, m);
    }
    uint32_t o0, o1;
    if      (q == 0) { o0 = a0; o1 = a1; }
    else if (q == 1) { o0 = a2; o1 = a3; }
    else if (q == 2) { o0 = a4; o1 = a5; }
    else             { o0 = a6; o1 = a7; }
    if (ADD) { o0 ^= ADD[i][2 * q]; o1 ^= ADD[i][2 * q + 1]; }
    uint2* op = reinterpret_cast<uint2*>(&OUT[i][2 * q]);
    *op = make_uint2(o0, o1);
}

// ------------------------- kernel: tree level 1 ----------------------------
// node n: P = A[2n+1]*A[2n], Q = A[2n+1] ^ I.   grid (32,1,4) x 256
__global__ __launch_bounds__(256) void k_tree_l1()
{
    int n = blockIdx.x, r0 = blockIdx.z * 64;
    tree_matmul64(g_A[2*n+1], g_A[2*n], nullptr, g_P[0][n], r0);
    int t = threadIdx.x;
    int li = t >> 2, g = (t & 3) * 2;
    int i = r0 + li;
#pragma unroll
    for (int j = 0; j < 2; ++j) {
        int w = g + j;
        uint32_t qv = g_A[2*n+1][i][w];
        if (w == (i >> 5)) qv ^= 1u << (i & 31);
        g_Q[0][n][i][w] = qv;
    }
}

// ------------------------- kernel: generic tree level ----------------------
// grid (nodes, 2, 4) x 256.   y==0: P = Ph*Pl ;  y==1: Q = Ph*Ql ^ Qh
__global__ __launch_bounds__(256) void k_tree_lv(int src, int dst)
{
    int n = blockIdx.x, isQ = blockIdx.y, r0 = blockIdx.z * 64;
    if (isQ)
        tree_matmul64(g_P[src][2*n+1], g_Q[src][2*n], g_Q[src][2*n+1], g_Q[dst][n], r0);
    else
        tree_matmul64(g_P[src][2*n+1], g_P[src][2*n], nullptr, g_P[dst][n], r0);
}

// ------------------------- kernel: transpose [P|Q] -> columns --------------
__global__ __launch_bounds__(256) void k_transpose()
{
    int j    = blockIdx.x * 8 + (threadIdx.x >> 5);  // 0..511
    int lane = threadIdx.x & 31;
    int jj = j & 255;
    const uint32_t (*src)[8] = (j < 256) ? g_P[1][0] : g_Q[1][0];
#pragma unroll
    for (int w = 0; w < 8; ++w) {
        uint32_t bit = (src[32 * w + lane][jj >> 5] >> (jj & 31)) & 1u;
        uint32_t col = __ballot_sync(FULLM, bit != 0);
        if (lane == 0) g_MT[j][w] = col;
    }
}

// ------------------------- kernel: batch apply + f32 output ----------------
// out_row = P*s ^ Q*c via stride-10 tables (LDS.64); output staged in the
// table buffer after passes complete. grid 256 x 256.
__global__ __launch_bounds__(256) void k_batch(float* __restrict__ out)
{
    __shared__ uint32_t Ts[64 * 16 * 10];     // 40960 B; reused as out staging
    int tid = threadIdx.x;
    int rowbase = blockIdx.x * 256;
    int row = rowbase + tid;
    uint32_t x[8];
    uint32_t a0 = 0, a1 = 0, a2 = 0, a3 = 0, a4 = 0, a5 = 0, a6 = 0, a7 = 0;
#pragma unroll
    for (int w = 0; w < 8; ++w) x[w] = g_S[row][w];

    int c = tid >> 2, g = (tid & 3) * 2;
    for (int pass = 0; pass < 2; ++pass) {
        __syncthreads();
        uint32_t b0[4], b1[4];
#pragma unroll
        for (int j = 0; j < 4; ++j) {
            b0[j] = g_MT[pass * 256 + 4 * c + j][g];
            b1[j] = g_MT[pass * 256 + 4 * c + j][g + 1];
        }
        int base = c * 160;
#pragma unroll
        for (int e = 0; e < 16; ++e) {
            uint32_t v0 = 0, v1 = 0;
            if (e & 1) { v0 ^= b0[0]; v1 ^= b1[0]; }
            if (e & 2) { v0 ^= b0[1]; v1 ^= b1[1]; }
            if (e & 4) { v0 ^= b0[2]; v1 ^= b1[2]; }
            if (e & 8) { v0 ^= b0[3]; v1 ^= b1[3]; }
            Ts[base + e * 10 + g] = v0; Ts[base + e * 10 + g + 1] = v1;
        }
        __syncthreads();
#pragma unroll 8
        for (int cc = 0; cc < 64; ++cc) {
            uint32_t idx = (x[cc >> 3] >> ((cc & 7) * 4)) & 15u;
            const uint2* e = reinterpret_cast<const uint2*>(&Ts[cc * 160 + idx * 10]);
            uint2 e0 = e[0], e1 = e[1], e2 = e[2], e3 = e[3];
            a0 ^= e0.x; a1 ^= e0.y; a2 ^= e1.x; a3 ^= e1.y;
            a4 ^= e2.x; a5 ^= e2.y; a6 ^= e3.x; a7 ^= e3.y;
        }
        if (pass == 0) {
#pragma unroll
            for (int w = 0; w < 8; ++w) x[w] = g_C[row][w];
        }
    }
    __syncthreads();                           // all lookups done; reuse Ts
    Ts[tid * 8 + 0] = a0; Ts[tid * 8 + 1] = a1;
    Ts[tid * 8 + 2] = a2; Ts[tid * 8 + 3] = a3;
    Ts[tid * 8 + 4] = a4; Ts[tid * 8 + 5] = a5;
    Ts[tid * 8 + 6] = a6; Ts[tid * 8 + 7] = a7;
    __syncthreads();

    // coalesced f32 expansion: each iter a warp writes 512B contiguous
#pragma unroll 4
    for (int it = 0; it < 64; ++it) {
        int flat = it * 1024 + tid * 4;
        int lrow = flat >> 8, i0 = flat & 255;
        uint32_t wv = Ts[lrow * 8 + (i0 >> 5)];
        int sh = i0 & 31;
        float4 v;
        v.x = ((wv >> sh)       & 1u) ? 1.0f : 0.0f;
        v.y = ((wv >> (sh + 1)) & 1u) ? 1.0f : 0.0f;
        v.z = ((wv >> (sh + 2)) & 1u) ? 1.0f : 0.0f;
        v.w = ((wv >> (sh + 3)) & 1u) ? 1.0f : 0.0f;
        *reinterpret_cast<float4*>(&out[(size_t)(rowbase + lrow) * 256 + i0]) = v;
    }
}

// ------------------------- kernel: exact fallback, block per flagged row ---
// 256 threads = 256 elements; state in smem; A rows prefetched 1 round ahead.
__global__ __launch_bounds__(256) void k_fixup(
    const float* __restrict__ bits, const float* __restrict__ noise,
    float* __restrict__ out)
{
    __shared__ uint32_t st[8];
    int nf = g_flagcnt;
    int i = threadIdx.x, w = i >> 5, lane = i & 31;
    for (int li = blockIdx.x; li < nf; li += gridDim.x) {
        int row = g_flaglist[li];
        float nv = noise[(size_t)row * 256 + i];
        float bv = bits [(size_t)row * 256 + i];
        uint32_t cbit = (uint32_t)(((int)floorf(nv)) & 1);
        float dd = ceilf(nv) - nv;
        bool danger = (dd > 0.0f && dd < FLAG_T);
        uint32_t b = __ballot_sync(FULLM, bv > 0.5f);
        if (lane == 0) st[w] = b;
        __syncthreads();

        uint4 a0 = *reinterpret_cast<const uint4*>(&g_A[0][i][0]);
        uint4 a1 = *reinterpret_cast<const uint4*>(&g_A[0][i][4]);
        uint4 p0, p1, m0, m1;
        if (danger) {
            p0 = *reinterpret_cast<const uint4*>(&g_Mp[0][i][0]);
            p1 = *reinterpret_cast<const uint4*>(&g_Mp[0][i][4]);
            m0 = *reinterpret_cast<const uint4*>(&g_Mm[0][i][0]);
            m1 = *reinterpret_cast<const uint4*>(&g_Mm[0][i][4]);
        }
        uint32_t bit = 0;
        for (int r = 0; r < RNDS; ++r) {
            uint32_t s0 = st[0], s1 = st[1], s2 = st[2], s3 = st[3];
            uint32_t s4 = st[4], s5 = st[5], s6 = st[6], s7 = st[7];
            __syncthreads();                    // all reads done before overwrite
            int pc = __popc(a0.x & s0) + __popc(a0.y & s1)
                   + __popc(a0.z & s2) + __popc(a0.w & s3)
                   + __popc(a1.x & s4) + __popc(a1.y & s5)
                   + __popc(a1.z & s6) + __popc(a1.w & s7);
            bit = ((uint32_t)pc & 1u) ^ cbit;
            if (danger) {
                int dot = __popc(p0.x & s0) - __popc(m0.x & s0)
                        + __popc(p0.y & s1) - __popc(m0.y & s1)
                        + __popc(p0.z & s2) - __popc(m0.z & s2)
                        + __popc(p0.w & s3) - __popc(m0.w & s3)
                        + __popc(p1.x & s4) - __popc(m1.x & s4)
                        + __popc(p1.y & s5) - __popc(m1.y & s5)
                        + __popc(p1.z & s6) - __popc(m1.z & s6)
                        + __popc(p1.w & s7) - __popc(m1.w & s7);
                bit = (uint32_t)(((int)floorf((float)dot + nv)) & 1);
            }
            if (r < RNDS - 1) {                 // prefetch next round (state-indep)
                a0 = *reinterpret_cast<const uint4*>(&g_A[r+1][i][0]);
                a1 = *reinterpret_cast<const uint4*>(&g_A[r+1][i][4]);
                if (danger) {
                    p0 = *reinterpret_cast<const uint4*>(&g_Mp[r+1][i][0]);
                    p1 = *reinterpret_cast<const uint4*>(&g_Mp[r+1][i][4]);
                    m0 = *reinterpret_cast<const uint4*>(&g_Mm[r+1][i][0]);
                    m1 = *reinterpret_cast<const uint4*>(&g_Mm[r+1][i][4]);
                }
            }
            uint32_t nb = __ballot_sync(FULLM, bit != 0);
            if (lane == 0) st[w] = nb;
            __syncthreads();
        }
        out[(size_t)row * 256 + i] = bit ? 1.0f : 0.0f;
        __syncthreads();
    }
}

// ------------------------- launch ------------------------------------------
extern "C" void kernel_launch(void* const* d_in, const int* in_sizes, int n_in,
                              void* d_out, int out_size)
{
    const float* bits  = (const float*)d_in[0];
    const float* noise = (const float*)d_in[1];
    const float* mats  = (const float*)d_in[2];
    float* out = (float*)d_out;

    k_reset<<<1, 1>>>();
    k_pack_all<<<10240, 256>>>(bits, noise, mats);
    k_tree_l1<<<dim3(32, 1, 4), 256>>>();
    k_tree_lv<<<dim3(16, 2, 4), 256>>>(0, 1);
    k_tree_lv<<<dim3( 8, 2, 4), 256>>>(1, 0);
    k_tree_lv<<<dim3( 4, 2, 4), 256>>>(0, 1);
    k_tree_lv<<<dim3( 2, 2, 4), 256>>>(1, 0);
    k_tree_lv<<<dim3( 1, 2, 4), 256>>>(0, 1);
    k_transpose<<<64, 256>>>();
    k_batch<<<256, 256>>>(out);
    k_fixup<<<2048, 256>>>(bits, noise, out);
}

// round 10
// speedup vs baseline: 3.8902x; 1.0188x over previous
#include <cuda_runtime.h>
#include <stdint.h>

// R9 resubmit of the R8-proposed source (persistent fused compose tree).
// R9 bench died in the GB300 container pre-compile; deadlock audit clean:
// grid 128 <= 148 SMs, serialized stream => all blocks resident, barrier
// monotonic + reset per launch. Same infra signature as R1/R3/R4/R6, all of
// which later passed verbatim.

#define BATCH 65536
#define RNDS  64
#define FULLM 0xffffffffu
// 2x margin over worst-case half-ulp (2^-16 for |sum| < 512)
#define FLAG_T 3.0517578125e-5f

// ------------------------- static device scratch ---------------------------
__device__ __align__(16) uint32_t g_A [RNDS][256][8];   // (M != 0)
__device__ __align__(16) uint32_t g_Mp[RNDS][256][8];   // (M == +1)
__device__ __align__(16) uint32_t g_Mm[RNDS][256][8];   // (M == -1)
__device__ __align__(16) uint32_t g_P [2][32][256][8];  // tree ping-pong: linear part
__device__ __align__(16) uint32_t g_Q [2][32][256][8];  // tree ping-pong: affine part
__device__ __align__(16) uint32_t g_S [BATCH][8];       // packed state bits
__device__ __align__(16) uint32_t g_C [BATCH][8];       // packed floor(noise)&1
__device__ __align__(16) uint32_t g_MT[512][8];         // columns of [P | Q]
__device__ int g_flagcnt;
__device__ int g_flaglist[BATCH];
__device__ unsigned int g_bar;                          // grid barrier counter

// ------------------------- kernel: reset -----------------------------------
__global__ void k_reset() { g_flagcnt = 0; g_bar = 0; }

// ------------------------- kernel: fused packing ---------------------------
// blocks [0,2048): pack matrices; blocks [2048,10240): pack state/noise+flags
__global__ __launch_bounds__(256) void k_pack_all(
    const float* __restrict__ bits, const float* __restrict__ noise,
    const float* __restrict__ mats)
{
    int b = blockIdx.x, t = threadIdx.x, lane = t & 31;
    if (b < 2048) {
        int gw = (b * 256 + t) >> 5;          // 0..16383 = r*256 + i
        int r = gw >> 8, i = gw & 255;
        const float* rowp = mats + (size_t)gw * 256;
#pragma unroll
        for (int w = 0; w < 8; ++w) {
            float v = rowp[w * 32 + lane];
            uint32_t ap = __ballot_sync(FULLM, v != 0.0f);
            uint32_t mp = __ballot_sync(FULLM, v >  0.5f);
            uint32_t mm = __ballot_sync(FULLM, v < -0.5f);
            if (lane == 0) { g_A[r][i][w] = ap; g_Mp[r][i][w] = mp; g_Mm[r][i][w] = mm; }
        }
    } else {
        int row = ((b - 2048) * 256 + t) >> 5;  // 0..65535
        bool bad = false;
#pragma unroll
        for (int w = 0; w < 8; ++w) {
            float bv = bits [(size_t)row * 256 + w * 32 + lane];
            float nv = noise[(size_t)row * 256 + w * 32 + lane];
            uint32_t sw = __ballot_sync(FULLM, bv > 0.5f);
            uint32_t cw = __ballot_sync(FULLM, (((int)floorf(nv)) & 1) != 0);
            float d = ceilf(nv) - nv;
            bad = bad || (d > 0.0f && d < FLAG_T);
            if (lane == 0) { g_S[row][w] = sw; g_C[row][w] = cw; }
        }
        uint32_t anyb = __ballot_sync(FULLM, bad);
        if (lane == 0 && anyb) {
            int idx = atomicAdd(&g_flagcnt, 1);
            g_flaglist[idx] = row;
        }
    }
}

// ------------------------- grid barrier (all 128 blocks resident) ----------
__device__ __forceinline__ void gridbar(int target)
{
    __syncthreads();
    if (threadIdx.x == 0) {
        __threadfence();
        atomicAdd(&g_bar, 1u);
        while (*((volatile unsigned int*)&g_bar) < (unsigned)target)
            __nanosleep(64);
    }
    __syncthreads();
}

// ------------------------- 4-Russians matmul unit, TPR threads per row -----
// OUT rows [r0, r0 + 256/TPR) = H (x) B (^ ADD).  256 threads, smem table
// passed in (shared across template instantiations).  Cross-block tree data
// accessed with ldcg/stcg (L1 not coherent across SMs within one launch).
template<int TPR>
__device__ __forceinline__ void mm_unit(uint32_t* Ts,
    const uint32_t (*H)[8], const uint32_t (*B)[8],
    const uint32_t (*ADD)[8], uint32_t (*OUT)[8], int r0)
{
    constexpr int CPT = 64 / TPR;             // chunks per thread
    int t = threadIdx.x;
    {
        int c = t >> 2, g = (t & 3) * 2;      // build words g,g+1 of chunk c
        uint32_t b0[4], b1[4];
#pragma unroll
        for (int j = 0; j < 4; ++j) {
            b0[j] = __ldcg(&B[4 * c + j][g]);
            b1[j] = __ldcg(&B[4 * c + j][g + 1]);
        }
        int base = c * 160;
#pragma unroll
        for (int e = 0; e < 16; ++e) {
            uint32_t v0 = 0, v1 = 0;
            if (e & 1) { v0 ^= b0[0]; v1 ^= b1[0]; }
            if (e & 2) { v0 ^= b0[1]; v1 ^= b1[1]; }
            if (e & 4) { v0 ^= b0[2]; v1 ^= b1[2]; }
            if (e & 8) { v0 ^= b0[3]; v1 ^= b1[3]; }
            Ts[base + e * 10 + g] = v0; Ts[base + e * 10 + g + 1] = v1;
        }
    }
    __syncthreads();

    int row = t / TPR, q = t % TPR;
    int i = r0 + row;
    int nb0 = q * CPT;                        // first nibble (chunk) index
    uint32_t hA = __ldcg(&H[i][nb0 >> 3]);
    uint32_t hB = (CPT == 16) ? __ldcg(&H[i][(nb0 >> 3) + 1]) : 0u;
    uint32_t a0 = 0, a1 = 0, a2 = 0, a3 = 0, a4 = 0, a5 = 0, a6 = 0, a7 = 0;
#pragma unroll
    for (int k = 0; k < CPT; ++k) {
        int nib = nb0 + k;
        uint32_t hw = (CPT == 16 && k >= 8) ? hB : hA;
        uint32_t idx = (hw >> ((nib & 7) * 4)) & 15u;
        const uint2* e = reinterpret_cast<const uint2*>(&Ts[nib * 160 + idx * 10]);
        uint2 e0 = e[0], e1 = e[1], e2 = e[2], e3 = e[3];
        a0 ^= e0.x; a1 ^= e0.y; a2 ^= e1.x; a3 ^= e1.y;
        a4 ^= e2.x; a5 ^= e2.y; a6 ^= e3.x; a7 ^= e3.y;
    }
#pragma unroll
    for (int m = 1; m < TPR; m <<= 1) {
        a0 ^= __shfl_xor_sync(FULLM, a0, m); a1 ^= __shfl_xor_sync(FULLM, a1, m);
        a2 ^= __shfl_xor_sync(FULLM, a2, m); a3 ^= __shfl_xor_sync(FULLM, a3, m);
        a4 ^= __shfl_xor_sync(FULLM, a4, m); a5 ^= __shfl_xor_sync(FULLM, a5, m);
        a6 ^= __shfl_xor_sync(FULLM, a6, m); a7 ^= __shfl_xor_sync(FULLM, a7, m);
    }
    if (q < 4) {
        uint32_t o0, o1;
        if      (q == 0) { o0 = a0; o1 = a1; }
        else if (q == 1) { o0 = a2; o1 = a3; }
        else if (q == 2) { o0 = a4; o1 = a5; }
        else             { o0 = a6; o1 = a7; }
        if (ADD) {
            uint2 ad = __ldcg(reinterpret_cast<const uint2*>(&ADD[i][2 * q]));
            o0 ^= ad.x; o1 ^= ad.y;
        }
        __stcg(reinterpret_cast<uint2*>(&OUT[i][2 * q]), make_uint2(o0, o1));
    }
}

// ------------------------- kernel: full compose tree + transpose -----------
// grid 128 x 256.  6 levels with grid barriers, then column transpose.
__global__ __launch_bounds__(256) void k_compose()
{
    __shared__ uint32_t Ts[64 * 16 * 10];     // 40960 B, shared by all levels
    int b = blockIdx.x, t = threadIdx.x;

    // Level 1: 32 nodes x 4 rowsplits.  P = A[2n+1]*A[2n]; Q = A[2n+1]^I.
    {
        int n = b >> 2, r0 = (b & 3) * 64;
        mm_unit<4>(Ts, g_A[2*n+1], g_A[2*n], nullptr, g_P[0][n], r0);
        int li = t >> 2, g = (t & 3) * 2;
        int i = r0 + li;
#pragma unroll
        for (int j = 0; j < 2; ++j) {
            int w = g + j;
            uint32_t qv = g_A[2*n+1][i][w];
            if (w == (i >> 5)) qv ^= 1u << (i & 31);
            __stcg(&g_Q[0][n][i][w], qv);
        }
    }
    gridbar(128);

    // Level 2: 16 nodes x {P,Q} x 4 rowsplits, buf 0 -> 1
    {
        int n = b >> 3, isQ = (b >> 2) & 1, r0 = (b & 3) * 64;
        if (isQ) mm_unit<4>(Ts, g_P[0][2*n+1], g_Q[0][2*n], g_Q[0][2*n+1], g_Q[1][n], r0);
        else     mm_unit<4>(Ts, g_P[0][2*n+1], g_P[0][2*n], nullptr,       g_P[1][n], r0);
    }
    gridbar(256);

    // Level 3: 8 nodes x {P,Q} x 8 rowsplits, buf 1 -> 0
    {
        int n = b >> 4, isQ = (b >> 3) & 1, r0 = (b & 7) * 32;
        if (isQ) mm_unit<8>(Ts, g_P[1][2*n+1], g_Q[1][2*n], g_Q[1][2*n+1], g_Q[0][n], r0);
        else     mm_unit<8>(Ts, g_P[1][2*n+1], g_P[1][2*n], nullptr,       g_P[0][n], r0);
    }
    gridbar(384);

    // Level 4: 4 nodes x {P,Q} x 16 rowsplits, buf 0 -> 1
    {
        int n = b >> 5, isQ = (b >> 4) & 1, r0 = (b & 15) * 16;
        if (isQ) mm_unit<16>(Ts, g_P[0][2*n+1], g_Q[0][2*n], g_Q[0][2*n+1], g_Q[1][n], r0);
        else     mm_unit<16>(Ts, g_P[0][2*n+1], g_P[0][2*n], nullptr,       g_P[1][n], r0);
    }
    gridbar(512);

    // Level 5: 2 nodes x {P,Q} x 32 rowsplits, buf 1 -> 0
    {
        int n = b >> 6, isQ = (b >> 5) & 1, r0 = (b & 31) * 8;
        if (isQ) mm_unit<32>(Ts, g_P[1][2*n+1], g_Q[1][2*n], g_Q[1][2*n+1], g_Q[0][n], r0);
        else     mm_unit<32>(Ts, g_P[1][2*n+1], g_P[1][2*n], nullptr,       g_P[0][n], r0);
    }
    gridbar(640);

    // Level 6: 1 node x {P,Q} x 32 rowsplits on blocks [0,64), buf 0 -> 1
    if (b < 64) {
        int isQ = (b >> 5) & 1, r0 = (b & 31) * 8;
        if (isQ) mm_unit<32>(Ts, g_P[0][1], g_Q[0][0], g_Q[0][1], g_Q[1][0], r0);
        else     mm_unit<32>(Ts, g_P[0][1], g_P[0][0], nullptr,   g_P[1][0], r0);
    }
    gridbar(768);

    // Transpose [P|Q] -> columns on blocks [0,64): warp per column
    if (b < 64) {
        int j    = b * 8 + (t >> 5);          // 0..511
        int lane = t & 31;
        int jj = j & 255;
        const uint32_t (*src)[8] = (j < 256) ? g_P[1][0] : g_Q[1][0];
#pragma unroll
        for (int w = 0; w < 8; ++w) {
            uint32_t bit = (__ldcg(&src[32 * w + lane][jj >> 5]) >> (jj & 31)) & 1u;
            uint32_t col = __ballot_sync(FULLM, bit != 0);
            if (lane == 0) g_MT[j][w] = col;
        }
    }
}

// ------------------------- kernel: batch apply + f32 output ----------------
// out_row = P*s ^ Q*c via stride-10 tables (LDS.64); output staged in the
// table buffer after passes complete. grid 256 x 256.
__global__ __launch_bounds__(256) void k_batch(float* __restrict__ out)
{
    __shared__ uint32_t Ts[64 * 16 * 10];     // 40960 B; reused as out staging
    int tid = threadIdx.x;
    int rowbase = blockIdx.x * 256;
    int row = rowbase + tid;
    uint32_t x[8];
    uint32_t a0 = 0, a1 = 0, a2 = 0, a3 = 0, a4 = 0, a5 = 0, a6 = 0, a7 = 0;
#pragma unroll
    for (int w = 0; w < 8; ++w) x[w] = g_S[row][w];

    int c = tid >> 2, g = (tid & 3) * 2;
    for (int pass = 0; pass < 2; ++pass) {
        __syncthreads();
        uint32_t b0[4], b1[4];
#pragma unroll
        for (int j = 0; j < 4; ++j) {
            b0[j] = g_MT[pass * 256 + 4 * c + j][g];
            b1[j] = g_MT[pass * 256 + 4 * c + j][g + 1];
        }
        int base = c * 160;
#pragma unroll
        for (int e = 0; e < 16; ++e) {
            uint32_t v0 = 0, v1 = 0;
            if (e & 1) { v0 ^= b0[0]; v1 ^= b1[0]; }
            if (e & 2) { v0 ^= b0[1]; v1 ^= b1[1]; }
            if (e & 4) { v0 ^= b0[2]; v1 ^= b1[2]; }
            if (e & 8) { v0 ^= b0[3]; v1 ^= b1[3]; }
            Ts[base + e * 10 + g] = v0; Ts[base + e * 10 + g + 1] = v1;
        }
        __syncthreads();
#pragma unroll 8
        for (int cc = 0; cc < 64; ++cc) {
            uint32_t idx = (x[cc >> 3] >> ((cc & 7) * 4)) & 15u;
            const uint2* e = reinterpret_cast<const uint2*>(&Ts[cc * 160 + idx * 10]);
            uint2 e0 = e[0], e1 = e[1], e2 = e[2], e3 = e[3];
            a0 ^= e0.x; a1 ^= e0.y; a2 ^= e1.x; a3 ^= e1.y;
            a4 ^= e2.x; a5 ^= e2.y; a6 ^= e3.x; a7 ^= e3.y;
        }
        if (pass == 0) {
#pragma unroll
            for (int w = 0; w < 8; ++w) x[w] = g_C[row][w];
        }
    }
    __syncthreads();                           // all lookups done; reuse Ts
    Ts[tid * 8 + 0] = a0; Ts[tid * 8 + 1] = a1;
    Ts[tid * 8 + 2] = a2; Ts[tid * 8 + 3] = a3;
    Ts[tid * 8 + 4] = a4; Ts[tid * 8 + 5] = a5;
    Ts[tid * 8 + 6] = a6; Ts[tid * 8 + 7] = a7;
    __syncthreads();

    // coalesced f32 expansion: each iter a warp writes 512B contiguous
#pragma unroll 4
    for (int it = 0; it < 64; ++it) {
        int flat = it * 1024 + tid * 4;
        int lrow = flat >> 8, i0 = flat & 255;
        uint32_t wv = Ts[lrow * 8 + (i0 >> 5)];
        int sh = i0 & 31;
        float4 v;
        v.x = ((wv >> sh)       & 1u) ? 1.0f : 0.0f;
        v.y = ((wv >> (sh + 1)) & 1u) ? 1.0f : 0.0f;
        v.z = ((wv >> (sh + 2)) & 1u) ? 1.0f : 0.0f;
        v.w = ((wv >> (sh + 3)) & 1u) ? 1.0f : 0.0f;
        *reinterpret_cast<float4*>(&out[(size_t)(rowbase + lrow) * 256 + i0]) = v;
    }
}

// ------------------------- kernel: exact fallback, block per flagged row ---
// 256 threads = 256 elements; state in smem; A rows prefetched 1 round ahead.
__global__ __launch_bounds__(256) void k_fixup(
    const float* __restrict__ bits, const float* __restrict__ noise,
    float* __restrict__ out)
{
    __shared__ uint32_t st[8];
    int nf = g_flagcnt;
    int i = threadIdx.x, w = i >> 5, lane = i & 31;
    for (int li = blockIdx.x; li < nf; li += gridDim.x) {
        int row = g_flaglist[li];
        float nv = noise[(size_t)row * 256 + i];
        float bv = bits [(size_t)row * 256 + i];
        uint32_t cbit = (uint32_t)(((int)floorf(nv)) & 1);
        float dd = ceilf(nv) - nv;
        bool danger = (dd > 0.0f && dd < FLAG_T);
        uint32_t b = __ballot_sync(FULLM, bv > 0.5f);
        if (lane == 0) st[w] = b;
        __syncthreads();

        uint4 a0 = *reinterpret_cast<const uint4*>(&g_A[0][i][0]);
        uint4 a1 = *reinterpret_cast<const uint4*>(&g_A[0][i][4]);
        uint4 p0, p1, m0, m1;
        if (danger) {
            p0 = *reinterpret_cast<const uint4*>(&g_Mp[0][i][0]);
            p1 = *reinterpret_cast<const uint4*>(&g_Mp[0][i][4]);
            m0 = *reinterpret_cast<const uint4*>(&g_Mm[0][i][0]);
            m1 = *reinterpret_cast<const uint4*>(&g_Mm[0][i][4]);
        }
        uint32_t bit = 0;
        for (int r = 0; r < RNDS; ++r) {
            uint32_t s0 = st[0], s1 = st[1], s2 = st[2], s3 = st[3];
            uint32_t s4 = st[4], s5 = st[5], s6 = st[6], s7 = st[7];
            __syncthreads();                    // all reads done before overwrite
            int pc = __popc(a0.x & s0) + __popc(a0.y & s1)
                   + __popc(a0.z & s2) + __popc(a0.w & s3)
                   + __popc(a1.x & s4) + __popc(a1.y & s5)
                   + __popc(a1.z & s6) + __popc(a1.w & s7);
            bit = ((uint32_t)pc & 1u) ^ cbit;
            if (danger) {
                int dot = __popc(p0.x & s0) - __popc(m0.x & s0)
                        + __popc(p0.y & s1) - __popc(m0.y & s1)
                        + __popc(p0.z & s2) - __popc(m0.z & s2)
                        + __popc(p0.w & s3) - __popc(m0.w & s3)
                        + __popc(p1.x & s4) - __popc(m1.x & s4)
                        + __popc(p1.y & s5) - __popc(m1.y & s5)
                        + __popc(p1.z & s6) - __popc(m1.z & s6)
                        + __popc(p1.w & s7) - __popc(m1.w & s7);
                bit = (uint32_t)(((int)floorf((float)dot + nv)) & 1);
            }
            if (r < RNDS - 1) {                 // prefetch next round (state-indep)
                a0 = *reinterpret_cast<const uint4*>(&g_A[r+1][i][0]);
                a1 = *reinterpret_cast<const uint4*>(&g_A[r+1][i][4]);
                if (danger) {
                    p0 = *reinterpret_cast<const uint4*>(&g_Mp[r+1][i][0]);
                    p1 = *reinterpret_cast<const uint4*>(&g_Mp[r+1][i][4]);
                    m0 = *reinterpret_cast<const uint4*>(&g_Mm[r+1][i][0]);
                    m1 = *reinterpret_cast<const uint4*>(&g_Mm[r+1][i][4]);
                }
            }
            uint32_t nb = __ballot_sync(FULLM, bit != 0);
            if (lane == 0) st[w] = nb;
            __syncthreads();
        }
        out[(size_t)row * 256 + i] = bit ? 1.0f : 0.0f;
        __syncthreads();
    }
}

// ------------------------- launch ------------------------------------------
extern "C" void kernel_launch(void* const* d_in, const int* in_sizes, int n_in,
                              void* d_out, int out_size)
{
    const float* bits  = (const float*)d_in[0];
    const float* noise = (const float*)d_in[1];
    const float* mats  = (const float*)d_in[2];
    float* out = (float*)d_out;

    k_reset<<<1, 1>>>();
    k_pack_all<<<10240, 256>>>(bits, noise, mats);
    k_compose<<<128, 256>>>();
    k_batch<<<256, 256>>>(out);
    k_fixup<<<2048, 256>>>(bits, noise, out);
}